// round 17
// baseline (speedup 1.0000x reference)
#include <cuda_runtime.h>
#include <cuda_fp16.h>
#include <mma.h>
#include <math.h>

using namespace nvcuda;

#define NMAX 50000
#define EMAX 1600000
#define HID  128
#define INC  16

// Scratch (allocation-free rule: __device__ globals)
__device__ __align__(16) __half g_h  [NMAX * HID];        // dinv-scaled pre-agg features (fp16)
__device__ __align__(16) __half g_x1h[(NMAX + 64) * HID]; // fp16(x1*dinv); mlp de-scales; pad=0
__device__ __align__(16) __half g_x2h[NMAX * HID];        // fp16(x2) for mlp a2 path
__device__ __align__(16) __half g_w2h[HID * HID];         // conv2_w in fp16
__device__ float g_dinv[NMAX];         // deg^-1/2 (incl. self loop)
__device__ int   g_deg [NMAX];         // in-degree (excl. self loop)
__device__ int   g_rowptr[NMAX];       // CSR segment starts (order-free alloc)
__device__ int   g_cursor[NMAX];       // fill cursors
__device__ int   g_eidx[EMAX];         // CSR: source node per incoming edge
__device__ int   g_is64;               // dtype flag: 1 if edge_index is int64
__device__ int   g_total;              // segment allocation cursor

// ---------------------------------------------------------------------------
// Fused init: zero deg/cursor, sniff edge dtype (warp 0, block 0), convert W2
// to fp16 (first 16384 threads).
__global__ void k_init(const int* __restrict__ w, int nwords, int n,
                       const float* __restrict__ w2) {
    int i = blockIdx.x * blockDim.x + threadIdx.x;
    if (i < n) { g_deg[i] = 0; g_cursor[i] = 0; }
    if (i == 0) g_total = 0;
    if (i < HID * HID) g_w2h[i] = __float2half(w2[i]);
    if (blockIdx.x == 0 && threadIdx.x < 32) {
        int lane = threadIdx.x;
        int idx  = 2 * lane + 1;
        int is0  = (idx < nwords) ? (w[idx] == 0) : 1;
        unsigned m = __ballot_sync(0xFFFFFFFFu, is0);
        if (lane == 0) g_is64 = (m == 0xFFFFFFFFu) ? 1 : 0;
    }
}

// Count in-degree straight from the input edge list.
__global__ void k_count(const void* __restrict__ ei, int E, int n) {
    int e = blockIdx.x * blockDim.x + threadIdx.x;
    if (e >= E) return;
    int c;
    if (g_is64) c = (int)((const long long*)ei)[(size_t)E + e];
    else        c = ((const int*)ei)[E + e];
    if (c < 0) c = 0; if (c >= n) c = n - 1;
    atomicAdd(&g_deg[c], 1);
}

// Segment-base allocation via warp-aggregated atomic; also computes dinv.
__global__ void k_alloc(int n) {
    int i    = blockIdx.x * blockDim.x + threadIdx.x;
    int lane = threadIdx.x & 31;
    int d = (i < n) ? g_deg[i] : 0;
    int s = d;
#pragma unroll
    for (int off = 1; off < 32; off <<= 1) {
        int v = __shfl_up_sync(0xFFFFFFFFu, s, off);
        if (lane >= off) s += v;
    }
    int warp_total = __shfl_sync(0xFFFFFFFFu, s, 31);
    int base = 0;
    if (lane == 31) base = atomicAdd(&g_total, warp_total);
    base = __shfl_sync(0xFFFFFFFFu, base, 31);
    if (i < n) {
        g_rowptr[i] = base + s - d;            // exclusive within warp
        g_dinv[i]   = rsqrtf((float)d + 1.0f); // +1: self loop
    }
}

// Fill CSR, re-deriving (r,c) from the input edge list.
__global__ void k_fill(const void* __restrict__ ei, int E, int n) {
    int e = blockIdx.x * blockDim.x + threadIdx.x;
    if (e >= E) return;
    int r, c;
    if (g_is64) {
        const long long* p = (const long long*)ei;
        r = (int)p[e];
        c = (int)p[(size_t)E + e];
    } else {
        const int* p = (const int*)ei;
        r = p[e];
        c = p[E + e];
    }
    if (r < 0) r = 0; if (r >= n) r = n - 1;
    if (c < 0) c = 0; if (c >= n) c = n - 1;
    int pos = g_rowptr[c] + atomicAdd(&g_cursor[c], 1);
    g_eidx[pos] = r;
}

// h = fp16( (x @ conv1_w) * dinv[node] )   (N x 16) @ (16 x 128); 16 nodes/block
__global__ void k_gemm1(const float* __restrict__ x, const float* __restrict__ w, int n) {
    __shared__ float xs[16 * INC];
    int base = blockIdx.x * 16;
    int tid  = threadIdx.x;
    for (int i = tid; i < 16 * INC; i += 128) {
        int node = base + i / INC;
        xs[i] = (node < n) ? x[node * INC + (i % INC)] : 0.f;
    }
    __syncthreads();
    float acc[16];
#pragma unroll
    for (int j = 0; j < 16; j++) acc[j] = 0.f;
#pragma unroll
    for (int k = 0; k < INC; k++) {
        float wv = w[k * HID + tid];
#pragma unroll
        for (int j = 0; j < 16; j++) acc[j] += xs[j * INC + k] * wv;
    }
    for (int j = 0; j < 16; j++) {
        int node = base + j;
        if (node < n)
            g_h[(size_t)node * HID + tid] = __float2half(acc[j] * g_dinv[node]);
    }
}

// conv2 GEMM on tensor cores: g_h = fp16( g_x1h @ W2 ), fp32 accumulate.
__global__ void __launch_bounds__(128) k_gemm2_mma(int n) {
    __shared__ float st[4][16 * HID];   // 32 KB: per-warp fp32 staging
    int warp = threadIdx.x >> 5;
    int lane = threadIdx.x & 31;
    int row0 = blockIdx.x * 64 + warp * 16;
    if (row0 >= n) return;              // warp-uniform exit

    wmma::fragment<wmma::accumulator, 16, 16, 16, float> acc[8];
#pragma unroll
    for (int j = 0; j < 8; j++) wmma::fill_fragment(acc[j], 0.f);

#pragma unroll
    for (int k = 0; k < 8; k++) {
        wmma::fragment<wmma::matrix_a, 16, 16, 16, __half, wmma::row_major> af;
        wmma::load_matrix_sync(af, g_x1h + (size_t)row0 * HID + k * 16, HID);
#pragma unroll
        for (int j = 0; j < 8; j++) {
            wmma::fragment<wmma::matrix_b, 16, 16, 16, __half, wmma::row_major> bf;
            wmma::load_matrix_sync(bf, g_w2h + (size_t)k * 16 * HID + j * 16, HID);
            wmma::mma_sync(acc[j], af, bf, acc[j]);
        }
    }

#pragma unroll
    for (int j = 0; j < 8; j++)
        wmma::store_matrix_sync(&st[warp][j * 16], acc[j], HID, wmma::mem_row_major);
    __syncwarp();

    for (int t = lane; t < 16 * HID / 2; t += 32) {
        int c2  = t * 2;
        int r   = c2 / HID;
        int c   = c2 % HID;
        int row = row0 + r;
        if (row < n) {
            __half2 hv = __floats2half2_rn(st[warp][r * HID + c],
                                           st[warp][r * HID + c + 1]);
            *reinterpret_cast<__half2*>(&g_h[(size_t)row * HID + c]) = hv;
        }
    }
}

// Aggregation: one warp per node, lane owns 4 halves (8B); fp32 accumulate,
// 16-way unrolled main loop + 4-way tail (avg degree ~32 -> tail matters).
// phase 0: write g_x1h = fp16(out*dc); phase 1: write g_x2h = fp16(out).
__global__ void k_gather(const float* __restrict__ b, int n, int phase) {
    int g    = blockIdx.x * blockDim.x + threadIdx.x;
    int i    = g >> 5;
    int lane = g & 31;
    if (i >= n) return;

    const __half* __restrict__ h = g_h;

    float dc    = g_dinv[i];
    int   start = g_rowptr[i];
    int   cnt   = g_deg[i];
    const int* __restrict__ ep = g_eidx + start;

    float4 acc = make_float4(0.f, 0.f, 0.f, 0.f);

    auto accum = [&](int s) {
        uint2 raw = reinterpret_cast<const uint2*>(h + (size_t)s * HID)[lane];
        __half2 p0 = *reinterpret_cast<__half2*>(&raw.x);
        __half2 p1 = *reinterpret_cast<__half2*>(&raw.y);
        float2 f0 = __half22float2(p0);
        float2 f1 = __half22float2(p1);
        acc.x += f0.x; acc.y += f0.y; acc.z += f1.x; acc.w += f1.y;
    };

    int k = 0;
    for (; k + 16 <= cnt; k += 16) {
        int s[16];
#pragma unroll
        for (int u = 0; u < 16; u++) s[u] = ep[k + u];
#pragma unroll
        for (int u = 0; u < 16; u++) accum(s[u]);
    }
    for (; k + 4 <= cnt; k += 4) {
        int s0 = ep[k], s1 = ep[k + 1], s2 = ep[k + 2], s3 = ep[k + 3];
        accum(s0); accum(s1); accum(s2); accum(s3);
    }
    for (; k < cnt; k++) accum(ep[k]);

    // self loop (h pre-scaled): + h_scaled[i]; then * dc
    accum(i);
    acc.x *= dc; acc.y *= dc; acc.z *= dc; acc.w *= dc;

    const float4 bv = reinterpret_cast<const float4*>(b)[lane];
    acc.x = fmaxf(acc.x + bv.x, 0.f);
    acc.y = fmaxf(acc.y + bv.y, 0.f);
    acc.z = fmaxf(acc.z + bv.z, 0.f);
    acc.w = fmaxf(acc.w + bv.w, 0.f);

    if (phase == 0) {
        __half2 h01 = __floats2half2_rn(acc.x * dc, acc.y * dc);
        __half2 h23 = __floats2half2_rn(acc.z * dc, acc.w * dc);
        __half2* dst = reinterpret_cast<__half2*>(g_x1h + (size_t)i * HID);
        dst[lane * 2]     = h01;
        dst[lane * 2 + 1] = h23;
    } else {
        __half2 h01 = __floats2half2_rn(acc.x, acc.y);
        __half2 h23 = __floats2half2_rn(acc.z, acc.w);
        __half2* dst = reinterpret_cast<__half2*>(g_x2h + (size_t)i * HID);
        dst[lane * 2]     = h01;
        dst[lane * 2 + 1] = h23;
    }
}

// ---------------------------------------------------------------------------
// Fused MLP heads. Feature rows staged through padded smem (coalesced gmem
// loads, conflict-free LDS); weights read as uniform __ldg float4 broadcasts.
// One thread per node.
#define XH_STRIDE 65   // half2 units per staged row (64 + 1 pad): t*65 mod 32 = t
#define X_STRIDE  17   // floats per staged x row (16 + 1 pad)
__global__ void __launch_bounds__(128) k_mlp(
                      const float* __restrict__ x,
                      const float* __restrict__ ln1w, const float* __restrict__ ln1b,
                      const float* __restrict__ ln2w, const float* __restrict__ ln2b,
                      const float* __restrict__ na1w, const float* __restrict__ na1b,
                      const float* __restrict__ na2w, const float* __restrict__ na2b,
                      const float* __restrict__ na3w, const float* __restrict__ na3b,
                      const float* __restrict__ na4w, const float* __restrict__ na4b,
                      const float* __restrict__ f1w,  const float* __restrict__ f1b,
                      const float* __restrict__ f2w,  const float* __restrict__ f2b,
                      const float* __restrict__ f3w,  const float* __restrict__ f3b,
                      float* __restrict__ out, int n) {
    __shared__ __half2 sxh[128 * XH_STRIDE];   // 33280 B: x1h then x2h rows
    __shared__ float   sx [128 * X_STRIDE];    //  8704 B: x rows

    int tid  = threadIdx.x;
    int base = blockIdx.x * 128;
    int i    = base + tid;
    bool live = (i < n);

    // stage x rows (coalesced)
    for (int t = tid; t < 128 * INC; t += 128) {
        int row = t / INC, col = t % INC;
        int node = base + row;
        sx[row * X_STRIDE + col] = (node < n) ? x[(size_t)node * INC + col] : 0.f;
    }
    // stage x1h rows (coalesced, half2 units)
    for (int t = tid; t < 128 * 64; t += 128) {
        int row = t >> 6, col = t & 63;
        int node = base + row;
        sxh[row * XH_STRIDE + col] = (node < n)
            ? reinterpret_cast<const __half2*>(g_x1h + (size_t)node * HID)[col]
            : __floats2half2_rn(0.f, 0.f);
    }
    __syncthreads();

    float xf[48];

    // --- gg path (x: 16 -> 32 -> 16) ---
    {
        float xin[INC];
#pragma unroll
        for (int k = 0; k < INC; k++) xin[k] = sx[tid * X_STRIDE + k];
        float h32[32];
#pragma unroll
        for (int j4 = 0; j4 < 8; j4++) {
            float4 a = __ldg((const float4*)(ln1b + j4 * 4));
#pragma unroll
            for (int k = 0; k < INC; k++) {
                float4 wv = __ldg((const float4*)(ln1w + k * 32 + j4 * 4));
                a.x += xin[k] * wv.x; a.y += xin[k] * wv.y;
                a.z += xin[k] * wv.z; a.w += xin[k] * wv.w;
            }
            h32[j4 * 4 + 0] = fmaxf(a.x, 0.f);
            h32[j4 * 4 + 1] = fmaxf(a.y, 0.f);
            h32[j4 * 4 + 2] = fmaxf(a.z, 0.f);
            h32[j4 * 4 + 3] = fmaxf(a.w, 0.f);
        }
#pragma unroll
        for (int j4 = 0; j4 < 4; j4++) {
            float4 a = __ldg((const float4*)(ln2b + j4 * 4));
#pragma unroll
            for (int k = 0; k < 32; k++) {
                float4 wv = __ldg((const float4*)(ln2w + k * 16 + j4 * 4));
                a.x += h32[k] * wv.x; a.y += h32[k] * wv.y;
                a.z += h32[k] * wv.z; a.w += h32[k] * wv.w;
            }
            xf[j4 * 4 + 0] = fmaxf(a.x, 0.f);
            xf[j4 * 4 + 1] = fmaxf(a.y, 0.f);
            xf[j4 * 4 + 2] = fmaxf(a.z, 0.f);
            xf[j4 * 4 + 3] = fmaxf(a.w, 0.f);
        }
    }

    // --- a1 path (x1 = x1h / dinv: 128 -> 16 -> 16) ---
    {
        float rdc = live ? (1.0f / g_dinv[i]) : 0.f;
        float4 t4[4];
#pragma unroll
        for (int j4 = 0; j4 < 4; j4++) t4[j4] = __ldg((const float4*)(na1b + j4 * 4));
        for (int k2 = 0; k2 < 64; k2++) {
            float2 f = __half22float2(sxh[tid * XH_STRIDE + k2]);
            float x0 = f.x * rdc, x1v = f.y * rdc;
#pragma unroll
            for (int j4 = 0; j4 < 4; j4++) {
                float4 w0 = __ldg((const float4*)(na1w + (k2 * 2) * 16 + j4 * 4));
                float4 w1 = __ldg((const float4*)(na1w + (k2 * 2 + 1) * 16 + j4 * 4));
                t4[j4].x += x0 * w0.x + x1v * w1.x;
                t4[j4].y += x0 * w0.y + x1v * w1.y;
                t4[j4].z += x0 * w0.z + x1v * w1.z;
                t4[j4].w += x0 * w0.w + x1v * w1.w;
            }
        }
        float t[16];
#pragma unroll
        for (int j4 = 0; j4 < 4; j4++) {
            t[j4 * 4 + 0] = fmaxf(t4[j4].x, 0.f);
            t[j4 * 4 + 1] = fmaxf(t4[j4].y, 0.f);
            t[j4 * 4 + 2] = fmaxf(t4[j4].z, 0.f);
            t[j4 * 4 + 3] = fmaxf(t4[j4].w, 0.f);
        }
#pragma unroll
        for (int j4 = 0; j4 < 4; j4++) {
            float4 a = __ldg((const float4*)(na2b + j4 * 4));
#pragma unroll
            for (int k = 0; k < 16; k++) {
                float4 wv = __ldg((const float4*)(na2w + k * 16 + j4 * 4));
                a.x += t[k] * wv.x; a.y += t[k] * wv.y;
                a.z += t[k] * wv.z; a.w += t[k] * wv.w;
            }
            xf[16 + j4 * 4 + 0] = fmaxf(a.x, 0.f);
            xf[16 + j4 * 4 + 1] = fmaxf(a.y, 0.f);
            xf[16 + j4 * 4 + 2] = fmaxf(a.z, 0.f);
            xf[16 + j4 * 4 + 3] = fmaxf(a.w, 0.f);
        }
    }

    // restage: x2h rows into the same buffer
    __syncthreads();
    for (int t = tid; t < 128 * 64; t += 128) {
        int row = t >> 6, col = t & 63;
        int node = base + row;
        sxh[row * XH_STRIDE + col] = (node < n)
            ? reinterpret_cast<const __half2*>(g_x2h + (size_t)node * HID)[col]
            : __floats2half2_rn(0.f, 0.f);
    }
    __syncthreads();

    // --- a2 path (x2h: 128 -> 16 -> 16) ---
    {
        float4 t4[4];
#pragma unroll
        for (int j4 = 0; j4 < 4; j4++) t4[j4] = __ldg((const float4*)(na3b + j4 * 4));
        for (int k2 = 0; k2 < 64; k2++) {
            float2 f = __half22float2(sxh[tid * XH_STRIDE + k2]);
#pragma unroll
            for (int j4 = 0; j4 < 4; j4++) {
                float4 w0 = __ldg((const float4*)(na3w + (k2 * 2) * 16 + j4 * 4));
                float4 w1 = __ldg((const float4*)(na3w + (k2 * 2 + 1) * 16 + j4 * 4));
                t4[j4].x += f.x * w0.x + f.y * w1.x;
                t4[j4].y += f.x * w0.y + f.y * w1.y;
                t4[j4].z += f.x * w0.z + f.y * w1.z;
                t4[j4].w += f.x * w0.w + f.y * w1.w;
            }
        }
        float t[16];
#pragma unroll
        for (int j4 = 0; j4 < 4; j4++) {
            t[j4 * 4 + 0] = fmaxf(t4[j4].x, 0.f);
            t[j4 * 4 + 1] = fmaxf(t4[j4].y, 0.f);
            t[j4 * 4 + 2] = fmaxf(t4[j4].z, 0.f);
            t[j4 * 4 + 3] = fmaxf(t4[j4].w, 0.f);
        }
#pragma unroll
        for (int j4 = 0; j4 < 4; j4++) {
            float4 a = __ldg((const float4*)(na4b + j4 * 4));
#pragma unroll
            for (int k = 0; k < 16; k++) {
                float4 wv = __ldg((const float4*)(na4w + k * 16 + j4 * 4));
                a.x += t[k] * wv.x; a.y += t[k] * wv.y;
                a.z += t[k] * wv.z; a.w += t[k] * wv.w;
            }
            xf[32 + j4 * 4 + 0] = fmaxf(a.x, 0.f);
            xf[32 + j4 * 4 + 1] = fmaxf(a.y, 0.f);
            xf[32 + j4 * 4 + 2] = fmaxf(a.z, 0.f);
            xf[32 + j4 * 4 + 3] = fmaxf(a.w, 0.f);
        }
    }

    // --- fusion head: 48 -> 64 -> 32 -> 1, sigmoid ---
    float h64[64];
#pragma unroll
    for (int j4 = 0; j4 < 16; j4++) {
        float4 a = __ldg((const float4*)(f1b + j4 * 4));
#pragma unroll
        for (int k = 0; k < 48; k++) {
            float4 wv = __ldg((const float4*)(f1w + k * 64 + j4 * 4));
            a.x += xf[k] * wv.x; a.y += xf[k] * wv.y;
            a.z += xf[k] * wv.z; a.w += xf[k] * wv.w;
        }
        h64[j4 * 4 + 0] = fmaxf(a.x, 0.f);
        h64[j4 * 4 + 1] = fmaxf(a.y, 0.f);
        h64[j4 * 4 + 2] = fmaxf(a.z, 0.f);
        h64[j4 * 4 + 3] = fmaxf(a.w, 0.f);
    }
    float h32b[32];
#pragma unroll
    for (int j4 = 0; j4 < 8; j4++) {
        float4 a = __ldg((const float4*)(f2b + j4 * 4));
#pragma unroll
        for (int k = 0; k < 64; k++) {
            float4 wv = __ldg((const float4*)(f2w + k * 32 + j4 * 4));
            a.x += h64[k] * wv.x; a.y += h64[k] * wv.y;
            a.z += h64[k] * wv.z; a.w += h64[k] * wv.w;
        }
        h32b[j4 * 4 + 0] = fmaxf(a.x, 0.f);
        h32b[j4 * 4 + 1] = fmaxf(a.y, 0.f);
        h32b[j4 * 4 + 2] = fmaxf(a.z, 0.f);
        h32b[j4 * 4 + 3] = fmaxf(a.w, 0.f);
    }
    float z = __ldg(f3b);
#pragma unroll
    for (int k = 0; k < 32; k++) z += h32b[k] * __ldg(f3w + k);
    if (live) out[i] = 1.f / (1.f + expf(-z));
}

// ---------------------------------------------------------------------------
extern "C" void kernel_launch(void* const* d_in, const int* in_sizes, int n_in,
                              void* d_out, int out_size) {
    const float* x        = (const float*)d_in[0];
    const void*  ei       = d_in[1];               // int32 OR int64 — detected on device
    const float* conv1_w  = (const float*)d_in[2];
    const float* conv1_b  = (const float*)d_in[3];
    const float* conv2_w  = (const float*)d_in[4];
    const float* conv2_b  = (const float*)d_in[5];
    const float* ln1_w = (const float*)d_in[6];   const float* ln1_b = (const float*)d_in[7];
    const float* ln2_w = (const float*)d_in[8];   const float* ln2_b = (const float*)d_in[9];
    const float* na1_w = (const float*)d_in[10];  const float* na1_b = (const float*)d_in[11];
    const float* na2_w = (const float*)d_in[12];  const float* na2_b = (const float*)d_in[13];
    const float* na3_w = (const float*)d_in[14];  const float* na3_b = (const float*)d_in[15];
    const float* na4_w = (const float*)d_in[16];  const float* na4_b = (const float*)d_in[17];
    const float* f1_w  = (const float*)d_in[18];  const float* f1_b  = (const float*)d_in[19];
    const float* f2_w  = (const float*)d_in[20];  const float* f2_b  = (const float*)d_in[21];
    const float* f3_w  = (const float*)d_in[22];  const float* f3_b  = (const float*)d_in[23];

    int n = in_sizes[0] / INC;
    int E = in_sizes[1] / 2;        // element count is 2E for either dtype
    if (E > EMAX) E = EMAX;
    if (n > NMAX) n = NMAX;

    int eb = (E + 255) / 256;
    int nb = (n + 255) / 256;

    // ---- CSR build ----
    k_init  <<<nb, 256>>>((const int*)ei, E * 2, n, conv2_w);
    k_count <<<eb, 256>>>(ei, E, n);
    k_alloc <<<nb, 256>>>(n);
    k_fill  <<<eb, 256>>>(ei, E, n);

    int gather_blocks = (n * 32 + 255) / 256;

    // ---- conv1 ----
    k_gemm1  <<<(n + 15) / 16, 128>>>(x, conv1_w, n);
    k_gather <<<gather_blocks, 256>>>(conv1_b, n, 0);

    // ---- conv2 (tensor cores) ----
    k_gemm2_mma <<<(n + 63) / 64, 128>>>(n);
    k_gather    <<<gather_blocks, 256>>>(conv2_b, n, 1);

    // ---- heads + fusion ----
    k_mlp<<<(n + 127) / 128, 128>>>(x,
        ln1_w, ln1_b, ln2_w, ln2_b,
        na1_w, na1_b, na2_w, na2_b,
        na3_w, na3_b, na4_w, na4_b,
        f1_w, f1_b, f2_w, f2_b, f3_w, f3_b,
        (float*)d_out, n);
}